// round 1
// baseline (speedup 1.0000x reference)
#include <cuda_runtime.h>

#define N_POIS 100000
#define N_HE   50000
#define NNZ    1600000
#define D      256
#define NL     2

// Scratch (allocation-free: device globals)
__device__ float g_msg_tar[(size_t)N_HE * D];    // 51.2 MB
__device__ float g_msg_src[(size_t)N_POIS * D];  // 102.4 MB
__device__ float g_embs[(size_t)N_POIS * D];     // 102.4 MB
__device__ float g_w[NL + 1];

// ---------------------------------------------------------------------------
// softmax of the 3 layer-attention logits -> g_w
__global__ void softmax_w_kernel(const float* __restrict__ attn) {
    float a0 = attn[0], a1 = attn[1], a2 = attn[2];
    float m = fmaxf(a0, fmaxf(a1, a2));
    float e0 = expf(a0 - m), e1 = expf(a1 - m), e2 = expf(a2 - m);
    float inv = 1.0f / (e0 + e1 + e2);
    g_w[0] = e0 * inv; g_w[1] = e1 * inv; g_w[2] = e2 * inv;
}

// ---------------------------------------------------------------------------
__global__ void __launch_bounds__(256) zero_kernel(float4* __restrict__ p, int n4) {
    int i = blockIdx.x * 256 + threadIdx.x;
    if (i < n4) p[i] = make_float4(0.f, 0.f, 0.f, 0.f);
}

// ---------------------------------------------------------------------------
// COO SpMM scatter: one warp per nonzero. Each lane handles 2 float4 chunks
// (lane*4 and lane*4+128) of the 256-wide row. Scatter via vector reduction.
__global__ void __launch_bounds__(256) spmm_kernel(
    const int*   __restrict__ rows,
    const int*   __restrict__ cols,
    const float* __restrict__ vals,
    const float* __restrict__ dense,
    float*       __restrict__ out)
{
    int e = (blockIdx.x * 256 + threadIdx.x) >> 5;
    if (e >= NNZ) return;
    int lane = threadIdx.x & 31;

    int   r = __ldg(rows + e);
    int   c = __ldg(cols + e);
    float v = __ldg(vals + e);

    const float4* src = reinterpret_cast<const float4*>(dense + (size_t)c * D) + lane;
    float4 a = __ldg(src);
    float4 b = __ldg(src + 32);

    float* dst = out + (size_t)r * D + lane * 4;
    asm volatile("red.global.add.v4.f32 [%0], {%1,%2,%3,%4};"
                 :: "l"(dst), "f"(a.x * v), "f"(a.y * v), "f"(a.z * v), "f"(a.w * v)
                 : "memory");
    asm volatile("red.global.add.v4.f32 [%0], {%1,%2,%3,%4};"
                 :: "l"(dst + 128), "f"(b.x * v), "f"(b.y * v), "f"(b.z * v), "f"(b.w * v)
                 : "memory");
}

// ---------------------------------------------------------------------------
// e = (relu(msg_src) * drop1 + prev) * drop2
// first==1: out = w0*prev + w[wi]*e ; also store e -> embs_out
// first==0: out += w[wi]*e
__global__ void __launch_bounds__(256) epilogue_kernel(
    const float4* __restrict__ msg_src,
    const float4* __restrict__ d1,
    const float4* __restrict__ prev,
    const float4* __restrict__ d2,
    float4*       __restrict__ embs_out,
    float4*       __restrict__ out,
    int wi, int first)
{
    int i = blockIdx.x * 256 + threadIdx.x;   // grid sized exactly: 6.4M float4
    float4 ms = __ldg(msg_src + i);
    float4 a  = __ldg(d1 + i);
    float4 p  = __ldg(prev + i);
    float4 b  = __ldg(d2 + i);

    float4 e;
    e.x = (fmaxf(ms.x, 0.f) * a.x + p.x) * b.x;
    e.y = (fmaxf(ms.y, 0.f) * a.y + p.y) * b.y;
    e.z = (fmaxf(ms.z, 0.f) * a.z + p.z) * b.z;
    e.w = (fmaxf(ms.w, 0.f) * a.w + p.w) * b.w;

    float w = g_w[wi];
    float4 o;
    if (first) {
        float w0 = g_w[0];
        o.x = w0 * p.x + w * e.x;
        o.y = w0 * p.y + w * e.y;
        o.z = w0 * p.z + w * e.z;
        o.w = w0 * p.w + w * e.w;
        embs_out[i] = e;
    } else {
        o = out[i];
        o.x = fmaf(w, e.x, o.x);
        o.y = fmaf(w, e.y, o.y);
        o.z = fmaf(w, e.z, o.z);
        o.w = fmaf(w, e.w, o.w);
    }
    out[i] = o;
}

// ---------------------------------------------------------------------------
extern "C" void kernel_launch(void* const* d_in, const int* in_sizes, int n_in,
                              void* d_out, int out_size)
{
    const float* pois      = (const float*)d_in[0];
    const float* tar_vals  = (const float*)d_in[1];
    const float* src_vals  = (const float*)d_in[2];
    const float* attn      = (const float*)d_in[3];
    const float* drop1     = (const float*)d_in[4];
    const float* drop2     = (const float*)d_in[5];
    const int*   tar_rows  = (const int*)d_in[6];
    const int*   tar_cols  = (const int*)d_in[7];
    const int*   src_rows  = (const int*)d_in[8];
    const int*   src_cols  = (const int*)d_in[9];
    float*       out       = (float*)d_out;

    float *msg_tar, *msg_src, *embs;
    cudaGetSymbolAddress((void**)&msg_tar, g_msg_tar);
    cudaGetSymbolAddress((void**)&msg_src, g_msg_src);
    cudaGetSymbolAddress((void**)&embs,    g_embs);

    const int n4_tar  = N_HE * D / 4;          // 3.2M
    const int n4_pois = N_POIS * D / 4;        // 6.4M
    const int spmm_blocks = NNZ / 8;           // 8 warps/block, exact
    const int epi_blocks  = n4_pois / 256;     // 25000, exact
    const size_t ld = (size_t)N_POIS * D;      // per-layer stride of drop masks

    softmax_w_kernel<<<1, 1>>>(attn);

    // ---- layer 0 (input = pois) ----
    zero_kernel<<<(n4_tar + 255) / 256, 256>>>((float4*)msg_tar, n4_tar);
    spmm_kernel<<<spmm_blocks, 256>>>(tar_rows, tar_cols, tar_vals, pois, msg_tar);
    zero_kernel<<<(n4_pois + 255) / 256, 256>>>((float4*)msg_src, n4_pois);
    spmm_kernel<<<spmm_blocks, 256>>>(src_rows, src_cols, src_vals, msg_tar, msg_src);
    epilogue_kernel<<<epi_blocks, 256>>>((const float4*)msg_src, (const float4*)drop1,
                                         (const float4*)pois, (const float4*)drop2,
                                         (float4*)embs, (float4*)out, 1, 1);

    // ---- layer 1 (input = embs) ----
    zero_kernel<<<(n4_tar + 255) / 256, 256>>>((float4*)msg_tar, n4_tar);
    spmm_kernel<<<spmm_blocks, 256>>>(tar_rows, tar_cols, tar_vals, embs, msg_tar);
    zero_kernel<<<(n4_pois + 255) / 256, 256>>>((float4*)msg_src, n4_pois);
    spmm_kernel<<<spmm_blocks, 256>>>(src_rows, src_cols, src_vals, msg_tar, msg_src);
    epilogue_kernel<<<epi_blocks, 256>>>((const float4*)msg_src, (const float4*)(drop1 + ld),
                                         (const float4*)embs, (const float4*)(drop2 + ld),
                                         (float4*)embs, (float4*)out, 2, 0);
}

// round 2
// speedup vs baseline: 2.0369x; 2.0369x over previous
#include <cuda_runtime.h>

#define N_POIS 100000
#define N_HE   50000
#define NNZ    1600000
#define D      256

// ---------------- scratch (allocation-free device globals) ----------------
__device__ float g_msg_tar[(size_t)N_HE * D];    // 51.2 MB
__device__ float g_embs[(size_t)N_POIS * D];     // 102.4 MB
__device__ float g_w[3];

__device__ int  g_ptr_tar[N_HE + 1];
__device__ int  g_cur_tar[N_HE];
__device__ int2 g_pairs_tar[NNZ];

__device__ int  g_ptr_src[N_POIS + 1];
__device__ int  g_cur_src[N_POIS];
__device__ int2 g_pairs_src[NNZ];

// ---------------------------------------------------------------------------
__global__ void softmax_w_kernel(const float* __restrict__ attn) {
    float a0 = attn[0], a1 = attn[1], a2 = attn[2];
    float m = fmaxf(a0, fmaxf(a1, a2));
    float e0 = expf(a0 - m), e1 = expf(a1 - m), e2 = expf(a2 - m);
    float inv = 1.0f / (e0 + e1 + e2);
    g_w[0] = e0 * inv; g_w[1] = e1 * inv; g_w[2] = e2 * inv;
}

__global__ void __launch_bounds__(256) zero_int_kernel(int* __restrict__ p, int n) {
    int i = blockIdx.x * 256 + threadIdx.x;
    if (i < n) p[i] = 0;
}

// counts accumulated at ptr[row+1]
__global__ void __launch_bounds__(256) hist_kernel(const int* __restrict__ rows,
                                                   int* __restrict__ cnt) {
    int e = blockIdx.x * 256 + threadIdx.x;
    if (e < NNZ) atomicAdd(&cnt[__ldg(rows + e) + 1], 1);
}

// single-block in-place inclusive scan (len <= ~100K)
__global__ void __launch_bounds__(1024) scan_kernel(int* __restrict__ p, int len) {
    __shared__ int sums[1024];
    int t = threadIdx.x;
    int chunk = (len + 1023) >> 10;
    int lo = t * chunk, hi = min(len, lo + chunk);
    int s = 0;
    for (int i = lo; i < hi; i++) s += p[i];
    sums[t] = s;
    __syncthreads();
    for (int d = 1; d < 1024; d <<= 1) {
        int v = (t >= d) ? sums[t - d] : 0;
        __syncthreads();
        sums[t] += v;
        __syncthreads();
    }
    int off = (t == 0) ? 0 : sums[t - 1];
    for (int i = lo; i < hi; i++) { off += p[i]; p[i] = off; }
}

__global__ void __launch_bounds__(256) copy_cur_kernel(const int* __restrict__ ptr,
                                                       int* __restrict__ cur, int n) {
    int i = blockIdx.x * 256 + threadIdx.x;
    if (i < n) cur[i] = ptr[i];
}

__global__ void __launch_bounds__(256) scatter_kernel(const int* __restrict__ rows,
                                                      const int* __restrict__ cols,
                                                      const float* __restrict__ vals,
                                                      int*  __restrict__ cur,
                                                      int2* __restrict__ pairs) {
    int e = blockIdx.x * 256 + threadIdx.x;
    if (e >= NNZ) return;
    int r = __ldg(rows + e);
    int pos = atomicAdd(&cur[r], 1);
    pairs[pos] = make_int2(__ldg(cols + e), __float_as_int(__ldg(vals + e)));
}

// ---------------------------------------------------------------------------
// Gather SpMM: one warp per output row. Each lane owns 8 floats (2 float4:
// lane and lane+32 within the 64-float4 row).
__device__ __forceinline__ void gather_row(const int* __restrict__ ptr,
                                           const int2* __restrict__ pairs,
                                           const float* __restrict__ dense,
                                           int row, int lane,
                                           float4& a0, float4& a1) {
    int start = __ldg(ptr + row), end = __ldg(ptr + row + 1);
    for (int base = start; base < end; base += 32) {
        int idx = min(base + lane, end - 1);
        int2 pr = __ldg(pairs + idx);
        int cnt = min(32, end - base);
        #pragma unroll 4
        for (int j = 0; j < cnt; j++) {
            int   c = __shfl_sync(0xffffffffu, pr.x, j);
            float v = __int_as_float(__shfl_sync(0xffffffffu, pr.y, j));
            const float4* s = reinterpret_cast<const float4*>(dense + (size_t)c * D) + lane;
            float4 x = __ldg(s);
            float4 y = __ldg(s + 32);
            a0.x = fmaf(v, x.x, a0.x); a0.y = fmaf(v, x.y, a0.y);
            a0.z = fmaf(v, x.z, a0.z); a0.w = fmaf(v, x.w, a0.w);
            a1.x = fmaf(v, y.x, a1.x); a1.y = fmaf(v, y.y, a1.y);
            a1.z = fmaf(v, y.z, a1.z); a1.w = fmaf(v, y.w, a1.w);
        }
    }
}

__global__ void __launch_bounds__(256) spmm_tar_kernel(const int*  __restrict__ ptr,
                                                       const int2* __restrict__ pairs,
                                                       const float* __restrict__ dense,
                                                       float* __restrict__ out) {
    int row = (blockIdx.x * 256 + threadIdx.x) >> 5;
    if (row >= N_HE) return;
    int lane = threadIdx.x & 31;
    float4 a0 = make_float4(0.f, 0.f, 0.f, 0.f), a1 = a0;
    gather_row(ptr, pairs, dense, row, lane, a0, a1);
    float4* o = reinterpret_cast<float4*>(out + (size_t)row * D) + lane;
    o[0] = a0; o[32] = a1;
}

// Fused src-SpMM + epilogue.
// LAYER 0: embs_out = e1 = (relu(msg)*d1 + prev)*d2          (prev = pois)
// LAYER 1: out = w0*pois + w1*prev + w2*e2                   (prev = embs/e1)
template<int LAYER>
__global__ void __launch_bounds__(256) spmm_src_fused_kernel(
    const int*  __restrict__ ptr,
    const int2* __restrict__ pairs,
    const float* __restrict__ dense,     // msg_tar
    const float4* __restrict__ d1,
    const float4* __restrict__ d2,
    const float4* __restrict__ prev,
    const float4* __restrict__ pois,
    float4* __restrict__ outp)
{
    int row = (blockIdx.x * 256 + threadIdx.x) >> 5;
    if (row >= N_POIS) return;
    int lane = threadIdx.x & 31;
    float4 a0 = make_float4(0.f, 0.f, 0.f, 0.f), a1 = a0;
    gather_row(ptr, pairs, dense, row, lane, a0, a1);

    size_t i0 = (size_t)row * (D / 4) + lane;
    float4 p0 = __ldg(prev + i0), p1 = __ldg(prev + i0 + 32);
    float4 m0 = __ldg(d1 + i0),   m1 = __ldg(d1 + i0 + 32);
    float4 q0 = __ldg(d2 + i0),   q1 = __ldg(d2 + i0 + 32);

    float4 e0, e1;
    e0.x = (fmaxf(a0.x, 0.f) * m0.x + p0.x) * q0.x;
    e0.y = (fmaxf(a0.y, 0.f) * m0.y + p0.y) * q0.y;
    e0.z = (fmaxf(a0.z, 0.f) * m0.z + p0.z) * q0.z;
    e0.w = (fmaxf(a0.w, 0.f) * m0.w + p0.w) * q0.w;
    e1.x = (fmaxf(a1.x, 0.f) * m1.x + p1.x) * q1.x;
    e1.y = (fmaxf(a1.y, 0.f) * m1.y + p1.y) * q1.y;
    e1.z = (fmaxf(a1.z, 0.f) * m1.z + p1.z) * q1.z;
    e1.w = (fmaxf(a1.w, 0.f) * m1.w + p1.w) * q1.w;

    if (LAYER == 0) {
        outp[i0]      = e0;
        outp[i0 + 32] = e1;
    } else {
        float w0 = g_w[0], w1 = g_w[1], w2 = g_w[2];
        float4 z0 = __ldg(pois + i0), z1 = __ldg(pois + i0 + 32);
        float4 o0, o1;
        o0.x = w0 * z0.x + w1 * p0.x + w2 * e0.x;
        o0.y = w0 * z0.y + w1 * p0.y + w2 * e0.y;
        o0.z = w0 * z0.z + w1 * p0.z + w2 * e0.z;
        o0.w = w0 * z0.w + w1 * p0.w + w2 * e0.w;
        o1.x = w0 * z1.x + w1 * p1.x + w2 * e1.x;
        o1.y = w0 * z1.y + w1 * p1.y + w2 * e1.y;
        o1.z = w0 * z1.z + w1 * p1.z + w2 * e1.z;
        o1.w = w0 * z1.w + w1 * p1.w + w2 * e1.w;
        outp[i0]      = o0;
        outp[i0 + 32] = o1;
    }
}

// ---------------------------------------------------------------------------
extern "C" void kernel_launch(void* const* d_in, const int* in_sizes, int n_in,
                              void* d_out, int out_size)
{
    const float* pois      = (const float*)d_in[0];
    const float* tar_vals  = (const float*)d_in[1];
    const float* src_vals  = (const float*)d_in[2];
    const float* attn      = (const float*)d_in[3];
    const float* drop1     = (const float*)d_in[4];
    const float* drop2     = (const float*)d_in[5];
    const int*   tar_rows  = (const int*)d_in[6];
    const int*   tar_cols  = (const int*)d_in[7];
    const int*   src_rows  = (const int*)d_in[8];
    const int*   src_cols  = (const int*)d_in[9];
    float*       out       = (float*)d_out;

    float *msg_tar, *embs;
    int *ptr_tar, *cur_tar, *ptr_src, *cur_src;
    int2 *pairs_tar, *pairs_src;
    cudaGetSymbolAddress((void**)&msg_tar,   g_msg_tar);
    cudaGetSymbolAddress((void**)&embs,      g_embs);
    cudaGetSymbolAddress((void**)&ptr_tar,   g_ptr_tar);
    cudaGetSymbolAddress((void**)&cur_tar,   g_cur_tar);
    cudaGetSymbolAddress((void**)&pairs_tar, g_pairs_tar);
    cudaGetSymbolAddress((void**)&ptr_src,   g_ptr_src);
    cudaGetSymbolAddress((void**)&cur_src,   g_cur_src);
    cudaGetSymbolAddress((void**)&pairs_src, g_pairs_src);

    const int nnz_blocks = (NNZ + 255) / 256;
    const size_t ld = (size_t)N_POIS * D;

    softmax_w_kernel<<<1, 1>>>(attn);

    // ---- CSR build: tar (rows in [0,N_HE)) ----
    zero_int_kernel<<<(N_HE + 1 + 255) / 256, 256>>>(ptr_tar, N_HE + 1);
    hist_kernel<<<nnz_blocks, 256>>>(tar_rows, ptr_tar);
    scan_kernel<<<1, 1024>>>(ptr_tar, N_HE + 1);
    copy_cur_kernel<<<(N_HE + 255) / 256, 256>>>(ptr_tar, cur_tar, N_HE);
    scatter_kernel<<<nnz_blocks, 256>>>(tar_rows, tar_cols, tar_vals, cur_tar, pairs_tar);

    // ---- CSR build: src (rows in [0,N_POIS)) ----
    zero_int_kernel<<<(N_POIS + 1 + 255) / 256, 256>>>(ptr_src, N_POIS + 1);
    hist_kernel<<<nnz_blocks, 256>>>(src_rows, ptr_src);
    scan_kernel<<<1, 1024>>>(ptr_src, N_POIS + 1);
    copy_cur_kernel<<<(N_POIS + 255) / 256, 256>>>(ptr_src, cur_src, N_POIS);
    scatter_kernel<<<nnz_blocks, 256>>>(src_rows, src_cols, src_vals, cur_src, pairs_src);

    const int tar_blocks = (N_HE * 32 + 255) / 256;      // warp per row
    const int src_blocks = (N_POIS * 32 + 255) / 256;

    // ---- layer 0 ----
    spmm_tar_kernel<<<tar_blocks, 256>>>(ptr_tar, pairs_tar, pois, msg_tar);
    spmm_src_fused_kernel<0><<<src_blocks, 256>>>(ptr_src, pairs_src, msg_tar,
        (const float4*)drop1, (const float4*)drop2,
        (const float4*)pois, (const float4*)pois, (float4*)embs);

    // ---- layer 1 ----
    spmm_tar_kernel<<<tar_blocks, 256>>>(ptr_tar, pairs_tar, embs, msg_tar);
    spmm_src_fused_kernel<1><<<src_blocks, 256>>>(ptr_src, pairs_src, msg_tar,
        (const float4*)(drop1 + ld), (const float4*)(drop2 + ld),
        (const float4*)embs, (const float4*)pois, (float4*)out);
}

// round 4
// speedup vs baseline: 2.3059x; 1.1321x over previous
#include <cuda_runtime.h>
#include <cuda_fp16.h>

#define N_POIS 100000
#define N_HE   50000
#define NNZ    1600000
#define D      256
#define NB     128          // scan blocks

// ---------------- scratch (allocation-free device globals) ----------------
__device__ __half g_pois_h[(size_t)N_POIS * D];   // 51.2 MB fp16 gather copy
__device__ __half g_msg_tar_h[(size_t)N_HE * D];  // 25.6 MB fp16 intermediate
__device__ __half g_embs_h[(size_t)N_POIS * D];   // 51.2 MB fp16 gather copy
__device__ float  g_embs[(size_t)N_POIS * D];     // 102.4 MB fp32 (epilogue prev)
__device__ float  g_w[3];

__device__ int  g_ptr_tar[N_HE + 1];
__device__ int  g_cur_tar[N_HE];
__device__ int2 g_pairs_tar[NNZ];
__device__ int  g_ptr_src[N_POIS + 1];
__device__ int  g_cur_src[N_POIS];
__device__ int2 g_pairs_src[NNZ];
__device__ int  g_bsums_tar[NB];
__device__ int  g_bsums_src[NB];

// ---------------------------------------------------------------------------
__device__ __forceinline__ unsigned pack2(float x, float y) {
    __half2 h = __floats2half2_rn(x, y);
    return *reinterpret_cast<unsigned*>(&h);
}
__device__ __forceinline__ float2 unpack2(unsigned u) {
    __half2 h = *reinterpret_cast<__half2*>(&u);
    return __half22float2(h);
}

// ---------------------------------------------------------------------------
__global__ void softmax_w_kernel(const float* __restrict__ attn) {
    float a0 = attn[0], a1 = attn[1], a2 = attn[2];
    float m = fmaxf(a0, fmaxf(a1, a2));
    float e0 = expf(a0 - m), e1 = expf(a1 - m), e2 = expf(a2 - m);
    float inv = 1.0f / (e0 + e1 + e2);
    g_w[0] = e0 * inv; g_w[1] = e1 * inv; g_w[2] = e2 * inv;
}

__global__ void __launch_bounds__(256) zero_int_kernel(int* __restrict__ p, int n) {
    int i = blockIdx.x * 256 + threadIdx.x;
    if (i < n) p[i] = 0;
}

__global__ void __launch_bounds__(256) hist_kernel(const int* __restrict__ rows,
                                                   int* __restrict__ cnt) {
    int e = blockIdx.x * 256 + threadIdx.x;
    if (e < NNZ) atomicAdd(&cnt[__ldg(rows + e) + 1], 1);
}

// ---- multi-block scan: A (block sums), B (scan sums), C (chunk scan+cur) ----
__global__ void __launch_bounds__(256) scanA_kernel(const int* __restrict__ p, int len,
                                                    int* __restrict__ bsums) {
    __shared__ int red[256];
    int chunk = (len + NB - 1) / NB;
    int lo = blockIdx.x * chunk, hi = min(len, lo + chunk);
    int sub = (chunk + 255) >> 8;
    int a = lo + threadIdx.x * sub, b = min(hi, a + sub);
    int s = 0;
    for (int i = a; i < b; i++) s += p[i];
    red[threadIdx.x] = s;
    __syncthreads();
    for (int d = 128; d > 0; d >>= 1) {
        if (threadIdx.x < d) red[threadIdx.x] += red[threadIdx.x + d];
        __syncthreads();
    }
    if (threadIdx.x == 0) bsums[blockIdx.x] = red[0];
}

__global__ void __launch_bounds__(NB) scanB_kernel(int* __restrict__ bsums) {
    __shared__ int s[NB];
    int t = threadIdx.x;
    s[t] = bsums[t];
    __syncthreads();
    int acc = s[t];
    for (int d = 1; d < NB; d <<= 1) {
        int v = (t >= d) ? s[t - d] : 0;
        __syncthreads();
        s[t] = acc = acc + v;
        __syncthreads();
        acc = s[t];
    }
    bsums[t] = (t == 0) ? 0 : s[t - 1];   // exclusive
}

__global__ void __launch_bounds__(256) scanC_kernel(int* __restrict__ p, int len,
                                                    const int* __restrict__ bsums,
                                                    int* __restrict__ cur) {
    __shared__ int s[256];
    int chunk = (len + NB - 1) / NB;
    int lo = blockIdx.x * chunk, hi = min(len, lo + chunk);
    int sub = (chunk + 255) >> 8;
    int a = lo + threadIdx.x * sub, b = min(hi, a + sub);
    int t = threadIdx.x;
    int sum = 0;
    for (int i = a; i < b; i++) sum += p[i];
    s[t] = sum;
    __syncthreads();
    int acc = s[t];
    for (int d = 1; d < 256; d <<= 1) {
        int v = (t >= d) ? s[t - d] : 0;
        __syncthreads();
        s[t] = acc = acc + v;
        __syncthreads();
        acc = s[t];
    }
    int off = bsums[blockIdx.x] + ((t == 0) ? 0 : s[t - 1]);
    for (int i = a; i < b; i++) {
        off += p[i];
        p[i] = off;
        if (i < len - 1) cur[i] = off;    // cur[row] = ptr[row]
    }
}

__global__ void __launch_bounds__(256) scatter_kernel(const int* __restrict__ rows,
                                                      const int* __restrict__ cols,
                                                      const float* __restrict__ vals,
                                                      int*  __restrict__ cur,
                                                      int2* __restrict__ pairs) {
    int e = blockIdx.x * 256 + threadIdx.x;
    if (e >= NNZ) return;
    int r = __ldg(rows + e);
    int pos = atomicAdd(&cur[r], 1);
    pairs[pos] = make_int2(__ldg(cols + e), __float_as_int(__ldg(vals + e)));
}

// fp32 -> fp16 copy (8 elems/thread), LINEAR layout
__global__ void __launch_bounds__(256) tohalf_kernel(const float4* __restrict__ in,
                                                     uint4* __restrict__ out, int n8) {
    int i = blockIdx.x * 256 + threadIdx.x;
    if (i >= n8) return;
    float4 a = __ldcs(in + 2 * i), b = __ldcs(in + 2 * i + 1);
    uint4 o;
    o.x = pack2(a.x, a.y); o.y = pack2(a.z, a.w);
    o.z = pack2(b.x, b.y); o.w = pack2(b.z, b.w);
    out[i] = o;
}

// ---------------------------------------------------------------------------
// fp16 gather: warp per row; lane owns CONTIGUOUS elements [lane*8, lane*8+8):
//   a0 = elements lane*8..+3, a1 = elements lane*8+4..+7  (linear layout)
__device__ __forceinline__ void gather_row_h(const int* __restrict__ ptr,
                                             const int2* __restrict__ pairs,
                                             const __half* __restrict__ dense,
                                             int row, int lane,
                                             float4& a0, float4& a1) {
    int start = __ldg(ptr + row), end = __ldg(ptr + row + 1);
    for (int base = start; base < end; base += 32) {
        int idx = min(base + lane, end - 1);
        int2 pr = __ldcs(pairs + idx);
        int cnt = min(32, end - base);
        #pragma unroll 4
        for (int j = 0; j < cnt; j++) {
            int   c = __shfl_sync(0xffffffffu, pr.x, j);
            float v = __int_as_float(__shfl_sync(0xffffffffu, pr.y, j));
            uint4 u = __ldg(reinterpret_cast<const uint4*>(dense + (size_t)c * D) + lane);
            float2 f0 = unpack2(u.x), f1 = unpack2(u.y);
            float2 f2 = unpack2(u.z), f3 = unpack2(u.w);
            a0.x = fmaf(v, f0.x, a0.x); a0.y = fmaf(v, f0.y, a0.y);
            a0.z = fmaf(v, f1.x, a0.z); a0.w = fmaf(v, f1.y, a0.w);
            a1.x = fmaf(v, f2.x, a1.x); a1.y = fmaf(v, f2.y, a1.y);
            a1.z = fmaf(v, f3.x, a1.z); a1.w = fmaf(v, f3.y, a1.w);
        }
    }
}

__global__ void __launch_bounds__(256) spmm_tar_kernel(const int*  __restrict__ ptr,
                                                       const int2* __restrict__ pairs,
                                                       const __half* __restrict__ dense,
                                                       __half* __restrict__ out) {
    int row = (blockIdx.x * 256 + threadIdx.x) >> 5;
    if (row >= N_HE) return;
    int lane = threadIdx.x & 31;
    float4 a0 = make_float4(0.f, 0.f, 0.f, 0.f), a1 = a0;
    gather_row_h(ptr, pairs, dense, row, lane, a0, a1);
    uint4 o;
    o.x = pack2(a0.x, a0.y); o.y = pack2(a0.z, a0.w);
    o.z = pack2(a1.x, a1.y); o.w = pack2(a1.z, a1.w);
    *(reinterpret_cast<uint4*>(out + (size_t)row * D) + lane) = o;   // linear
}

// Fused src-SpMM + epilogue.  a0/a1 are elements [lane*8, lane*8+8).
// LAYER 0: e = (relu(msg)*d1 + prev)*d2 ; embs=e (fp32) ; embs_h=e (fp16)
// LAYER 1: out = w0*pois + w1*prev + w2*e
template<int LAYER>
__global__ void __launch_bounds__(256) spmm_src_fused_kernel(
    const int*  __restrict__ ptr,
    const int2* __restrict__ pairs,
    const __half* __restrict__ dense,   // msg_tar_h
    const float4* __restrict__ d1,
    const float4* __restrict__ d2,
    const float4* __restrict__ prev,
    const float4* __restrict__ pois,
    float4* __restrict__ outp,
    uint4*  __restrict__ out_h)
{
    int row = (blockIdx.x * 256 + threadIdx.x) >> 5;
    if (row >= N_POIS) return;
    int lane = threadIdx.x & 31;
    float4 a0 = make_float4(0.f, 0.f, 0.f, 0.f), a1 = a0;
    gather_row_h(ptr, pairs, dense, row, lane, a0, a1);

    size_t i0 = (size_t)row * (D / 4) + 2 * lane;   // float4 pair for [lane*8, +8)
    float4 p0 = __ldg(prev + i0), p1 = __ldg(prev + i0 + 1);
    float4 m0 = __ldcs(d1 + i0),  m1 = __ldcs(d1 + i0 + 1);
    float4 q0 = __ldcs(d2 + i0),  q1 = __ldcs(d2 + i0 + 1);

    float4 e0, e1;
    e0.x = (fmaxf(a0.x, 0.f) * m0.x + p0.x) * q0.x;
    e0.y = (fmaxf(a0.y, 0.f) * m0.y + p0.y) * q0.y;
    e0.z = (fmaxf(a0.z, 0.f) * m0.z + p0.z) * q0.z;
    e0.w = (fmaxf(a0.w, 0.f) * m0.w + p0.w) * q0.w;
    e1.x = (fmaxf(a1.x, 0.f) * m1.x + p1.x) * q1.x;
    e1.y = (fmaxf(a1.y, 0.f) * m1.y + p1.y) * q1.y;
    e1.z = (fmaxf(a1.z, 0.f) * m1.z + p1.z) * q1.z;
    e1.w = (fmaxf(a1.w, 0.f) * m1.w + p1.w) * q1.w;

    if (LAYER == 0) {
        outp[i0]     = e0;
        outp[i0 + 1] = e1;
        uint4 h;
        h.x = pack2(e0.x, e0.y); h.y = pack2(e0.z, e0.w);
        h.z = pack2(e1.x, e1.y); h.w = pack2(e1.z, e1.w);
        out_h[(size_t)row * (D / 8) + lane] = h;    // linear
    } else {
        float w0 = g_w[0], w1 = g_w[1], w2 = g_w[2];
        float4 z0 = __ldcs(pois + i0), z1 = __ldcs(pois + i0 + 1);
        float4 o0, o1;
        o0.x = w0 * z0.x + w1 * p0.x + w2 * e0.x;
        o0.y = w0 * z0.y + w1 * p0.y + w2 * e0.y;
        o0.z = w0 * z0.z + w1 * p0.z + w2 * e0.z;
        o0.w = w0 * z0.w + w1 * p0.w + w2 * e0.w;
        o1.x = w0 * z1.x + w1 * p1.x + w2 * e1.x;
        o1.y = w0 * z1.y + w1 * p1.y + w2 * e1.y;
        o1.z = w0 * z1.z + w1 * p1.z + w2 * e1.z;
        o1.w = w0 * z1.w + w1 * p1.w + w2 * e1.w;
        outp[i0]     = o0;
        outp[i0 + 1] = o1;
    }
}

// ---------------------------------------------------------------------------
extern "C" void kernel_launch(void* const* d_in, const int* in_sizes, int n_in,
                              void* d_out, int out_size)
{
    const float* pois      = (const float*)d_in[0];
    const float* tar_vals  = (const float*)d_in[1];
    const float* src_vals  = (const float*)d_in[2];
    const float* attn      = (const float*)d_in[3];
    const float* drop1     = (const float*)d_in[4];
    const float* drop2     = (const float*)d_in[5];
    const int*   tar_rows  = (const int*)d_in[6];
    const int*   tar_cols  = (const int*)d_in[7];
    const int*   src_rows  = (const int*)d_in[8];
    const int*   src_cols  = (const int*)d_in[9];
    float*       out       = (float*)d_out;

    __half *pois_h, *msg_tar_h, *embs_h;
    float *embs;
    int *ptr_tar, *cur_tar, *ptr_src, *cur_src, *bs_tar, *bs_src;
    int2 *pairs_tar, *pairs_src;
    cudaGetSymbolAddress((void**)&pois_h,    g_pois_h);
    cudaGetSymbolAddress((void**)&msg_tar_h, g_msg_tar_h);
    cudaGetSymbolAddress((void**)&embs_h,    g_embs_h);
    cudaGetSymbolAddress((void**)&embs,      g_embs);
    cudaGetSymbolAddress((void**)&ptr_tar,   g_ptr_tar);
    cudaGetSymbolAddress((void**)&cur_tar,   g_cur_tar);
    cudaGetSymbolAddress((void**)&pairs_tar, g_pairs_tar);
    cudaGetSymbolAddress((void**)&ptr_src,   g_ptr_src);
    cudaGetSymbolAddress((void**)&cur_src,   g_cur_src);
    cudaGetSymbolAddress((void**)&pairs_src, g_pairs_src);
    cudaGetSymbolAddress((void**)&bs_tar,    g_bsums_tar);
    cudaGetSymbolAddress((void**)&bs_src,    g_bsums_src);

    const int nnz_blocks = (NNZ + 255) / 256;
    const size_t ld = (size_t)N_POIS * D;

    softmax_w_kernel<<<1, 1>>>(attn);

    // fp16 copy of pois (needed before layer-0 tar spmm)
    tohalf_kernel<<<(N_POIS * D / 8 + 255) / 256, 256>>>(
        (const float4*)pois, (uint4*)pois_h, N_POIS * D / 8);

    // ---- CSR build: tar ----
    zero_int_kernel<<<(N_HE + 1 + 255) / 256, 256>>>(ptr_tar, N_HE + 1);
    hist_kernel<<<nnz_blocks, 256>>>(tar_rows, ptr_tar);
    scanA_kernel<<<NB, 256>>>(ptr_tar, N_HE + 1, bs_tar);
    scanB_kernel<<<1, NB>>>(bs_tar);
    scanC_kernel<<<NB, 256>>>(ptr_tar, N_HE + 1, bs_tar, cur_tar);
    scatter_kernel<<<nnz_blocks, 256>>>(tar_rows, tar_cols, tar_vals, cur_tar, pairs_tar);

    // ---- CSR build: src ----
    zero_int_kernel<<<(N_POIS + 1 + 255) / 256, 256>>>(ptr_src, N_POIS + 1);
    hist_kernel<<<nnz_blocks, 256>>>(src_rows, ptr_src);
    scanA_kernel<<<NB, 256>>>(ptr_src, N_POIS + 1, bs_src);
    scanB_kernel<<<1, NB>>>(bs_src);
    scanC_kernel<<<NB, 256>>>(ptr_src, N_POIS + 1, bs_src, cur_src);
    scatter_kernel<<<nnz_blocks, 256>>>(src_rows, src_cols, src_vals, cur_src, pairs_src);

    const int tar_blocks = (N_HE * 32 + 255) / 256;
    const int src_blocks = (N_POIS * 32 + 255) / 256;

    // ---- layer 0 ----
    spmm_tar_kernel<<<tar_blocks, 256>>>(ptr_tar, pairs_tar, pois_h, msg_tar_h);
    spmm_src_fused_kernel<0><<<src_blocks, 256>>>(ptr_src, pairs_src, msg_tar_h,
        (const float4*)drop1, (const float4*)drop2,
        (const float4*)pois, (const float4*)pois,
        (float4*)embs, (uint4*)embs_h);

    // ---- layer 1 ----
    spmm_tar_kernel<<<tar_blocks, 256>>>(ptr_tar, pairs_tar, embs_h, msg_tar_h);
    spmm_src_fused_kernel<1><<<src_blocks, 256>>>(ptr_src, pairs_src, msg_tar_h,
        (const float4*)(drop1 + ld), (const float4*)(drop2 + ld),
        (const float4*)embs, (const float4*)pois,
        (float4*)out, nullptr);
}

// round 5
// speedup vs baseline: 3.3478x; 1.4519x over previous
#include <cuda_runtime.h>
#include <cuda_fp16.h>

#define N_POIS 100000
#define N_HE   50000
#define NNZ    1600000
#define D      256
#define NB     128          // scan blocks per matrix

// ---------------- scratch (allocation-free device globals) ----------------
__device__ __half g_pois_h[(size_t)N_POIS * D];   // 51.2 MB fp16 gather copy
__device__ __half g_msg_tar_h[(size_t)N_HE * D];  // 25.6 MB fp16 intermediate
__device__ __half g_embs_h[(size_t)N_POIS * D];   // 51.2 MB fp16 e1
__device__ float  g_w[3];

__device__ int  g_ptr_tar[N_HE + 1];
__device__ int  g_cur_tar[N_HE];
__device__ int2 g_pairs_tar[NNZ];
__device__ int  g_ptr_src[N_POIS + 1];
__device__ int  g_cur_src[N_POIS];
__device__ int2 g_pairs_src[NNZ];
__device__ int  g_bsums[2 * NB];

// ---------------------------------------------------------------------------
__device__ __forceinline__ unsigned pack2(float x, float y) {
    __half2 h = __floats2half2_rn(x, y);
    return *reinterpret_cast<unsigned*>(&h);
}
__device__ __forceinline__ float2 unpack2(unsigned u) {
    __half2 h = *reinterpret_cast<__half2*>(&u);
    return __half22float2(h);
}

// ---------------------------------------------------------------------------
__global__ void softmax_w_kernel(const float* __restrict__ attn) {
    float a0 = attn[0], a1 = attn[1], a2 = attn[2];
    float m = fmaxf(a0, fmaxf(a1, a2));
    float e0 = expf(a0 - m), e1 = expf(a1 - m), e2 = expf(a2 - m);
    float inv = 1.0f / (e0 + e1 + e2);
    g_w[0] = e0 * inv; g_w[1] = e1 * inv; g_w[2] = e2 * inv;
}

__global__ void __launch_bounds__(256) zero_both_kernel(int* __restrict__ a, int na,
                                                        int* __restrict__ b, int nb) {
    int i = blockIdx.x * 256 + threadIdx.x;
    if (i < na) a[i] = 0;
    if (i < nb) b[i] = 0;
}

__global__ void __launch_bounds__(256) hist_both_kernel(const int* __restrict__ rt,
                                                        const int* __restrict__ rs,
                                                        int* __restrict__ ct,
                                                        int* __restrict__ cs) {
    int e = blockIdx.x * 256 + threadIdx.x;
    if (e >= NNZ) return;
    atomicAdd(&ct[__ldg(rt + e) + 1], 1);
    atomicAdd(&cs[__ldg(rs + e) + 1], 1);
}

// ---- fused multi-block scan over both ptr arrays ----
// blocks [0,NB) -> tar, [NB,2NB) -> src ; bsums[0..NB) tar, [NB..2NB) src
__global__ void __launch_bounds__(256) scanA_kernel(int* __restrict__ pt, int lt,
                                                    int* __restrict__ ps, int ls,
                                                    int* __restrict__ bsums) {
    __shared__ int red[256];
    int m   = blockIdx.x / NB;
    int blk = blockIdx.x % NB;
    int* p  = m ? ps : pt;
    int len = m ? ls : lt;
    int chunk = (len + NB - 1) / NB;
    int lo = blk * chunk, hi = min(len, lo + chunk);
    int sub = (chunk + 255) >> 8;
    int a = lo + threadIdx.x * sub, b = min(hi, a + sub);
    int s = 0;
    for (int i = a; i < b; i++) s += p[i];
    red[threadIdx.x] = s;
    __syncthreads();
    for (int d = 128; d > 0; d >>= 1) {
        if (threadIdx.x < d) red[threadIdx.x] += red[threadIdx.x + d];
        __syncthreads();
    }
    if (threadIdx.x == 0) bsums[blockIdx.x] = red[0];
}

__global__ void __launch_bounds__(NB) scanB_kernel(int* __restrict__ bsums) {
    __shared__ int s[NB];
    int t = threadIdx.x;
    int* bs = bsums + blockIdx.x * NB;
    s[t] = bs[t];
    __syncthreads();
    int acc = s[t];
    for (int d = 1; d < NB; d <<= 1) {
        int v = (t >= d) ? s[t - d] : 0;
        __syncthreads();
        s[t] = acc = acc + v;
        __syncthreads();
        acc = s[t];
    }
    bs[t] = (t == 0) ? 0 : s[t - 1];   // exclusive
}

__global__ void __launch_bounds__(256) scanC_kernel(int* __restrict__ pt, int lt,
                                                    int* __restrict__ ps, int ls,
                                                    const int* __restrict__ bsums,
                                                    int* __restrict__ curt,
                                                    int* __restrict__ curs) {
    __shared__ int s[256];
    int m   = blockIdx.x / NB;
    int blk = blockIdx.x % NB;
    int* p   = m ? ps : pt;
    int len  = m ? ls : lt;
    int* cur = m ? curs : curt;
    int chunk = (len + NB - 1) / NB;
    int lo = blk * chunk, hi = min(len, lo + chunk);
    int sub = (chunk + 255) >> 8;
    int a = lo + threadIdx.x * sub, b = min(hi, a + sub);
    int t = threadIdx.x;
    int sum = 0;
    for (int i = a; i < b; i++) sum += p[i];
    s[t] = sum;
    __syncthreads();
    int acc = s[t];
    for (int d = 1; d < 256; d <<= 1) {
        int v = (t >= d) ? s[t - d] : 0;
        __syncthreads();
        s[t] = acc = acc + v;
        __syncthreads();
        acc = s[t];
    }
    int off = bsums[blockIdx.x] + ((t == 0) ? 0 : s[t - 1]);
    for (int i = a; i < b; i++) {
        off += p[i];
        p[i] = off;
        if (i < len - 1) cur[i] = off;    // cur[row] = ptr[row]
    }
}

__global__ void __launch_bounds__(256) scatter_both_kernel(
    const int* __restrict__ rt, const int* __restrict__ colt,
    const float* __restrict__ valt, int* __restrict__ curt, int2* __restrict__ pt,
    const int* __restrict__ rs, const int* __restrict__ cols,
    const float* __restrict__ vals, int* __restrict__ curs, int2* __restrict__ ps)
{
    int e = blockIdx.x * 256 + threadIdx.x;
    if (e >= NNZ) return;
    int r1 = __ldg(rt + e);
    int p1 = atomicAdd(&curt[r1], 1);
    pt[p1] = make_int2(__ldg(colt + e), __float_as_int(__ldg(valt + e)));
    int r2 = __ldg(rs + e);
    int p2 = atomicAdd(&curs[r2], 1);
    ps[p2] = make_int2(__ldg(cols + e), __float_as_int(__ldg(vals + e)));
}

// fp32 -> fp16 copy (8 elems/thread), LINEAR layout
__global__ void __launch_bounds__(256) tohalf_kernel(const float4* __restrict__ in,
                                                     uint4* __restrict__ out, int n8) {
    int i = blockIdx.x * 256 + threadIdx.x;
    if (i >= n8) return;
    float4 a = __ldcs(in + 2 * i), b = __ldcs(in + 2 * i + 1);
    uint4 o;
    o.x = pack2(a.x, a.y); o.y = pack2(a.z, a.w);
    o.z = pack2(b.x, b.y); o.w = pack2(b.z, b.w);
    out[i] = o;
}

// ---------------------------------------------------------------------------
// fp16 gather: warp per row; lane owns CONTIGUOUS elements [lane*8, lane*8+8).
// Pairs are read as uniform broadcast loads (all lanes same address, L1-hit).
__device__ __forceinline__ void gather_row_h(const int* __restrict__ ptr,
                                             const int2* __restrict__ pairs,
                                             const __half* __restrict__ dense,
                                             int row, int lane,
                                             float4& a0, float4& a1) {
    int start = __ldg(ptr + row), end = __ldg(ptr + row + 1);
    #pragma unroll 4
    for (int j = start; j < end; j++) {
        int2 pr = __ldg(pairs + j);                 // uniform across warp
        float v = __int_as_float(pr.y);
        uint4 u = __ldg(reinterpret_cast<const uint4*>(dense + (size_t)pr.x * D) + lane);
        float2 f0 = unpack2(u.x), f1 = unpack2(u.y);
        float2 f2 = unpack2(u.z), f3 = unpack2(u.w);
        a0.x = fmaf(v, f0.x, a0.x); a0.y = fmaf(v, f0.y, a0.y);
        a0.z = fmaf(v, f1.x, a0.z); a0.w = fmaf(v, f1.y, a0.w);
        a1.x = fmaf(v, f2.x, a1.x); a1.y = fmaf(v, f2.y, a1.y);
        a1.z = fmaf(v, f3.x, a1.z); a1.w = fmaf(v, f3.y, a1.w);
    }
}

__global__ void __launch_bounds__(256) spmm_tar_kernel(const int*  __restrict__ ptr,
                                                       const int2* __restrict__ pairs,
                                                       const __half* __restrict__ dense,
                                                       __half* __restrict__ out) {
    int row = (blockIdx.x * 256 + threadIdx.x) >> 5;
    if (row >= N_HE) return;
    int lane = threadIdx.x & 31;
    float4 a0 = make_float4(0.f, 0.f, 0.f, 0.f), a1 = a0;
    gather_row_h(ptr, pairs, dense, row, lane, a0, a1);
    uint4 o;
    o.x = pack2(a0.x, a0.y); o.y = pack2(a0.z, a0.w);
    o.z = pack2(a1.x, a1.y); o.w = pack2(a1.z, a1.w);
    *(reinterpret_cast<uint4*>(out + (size_t)row * D) + lane) = o;   // linear
}

// Fused src-SpMM + epilogue.  a0/a1 are elements [lane*8, lane*8+8).
// LAYER 0: e1 = (relu(msg)*d1 + pois)*d2 ; embs_h = fp16(e1)
// LAYER 1: e2 = (relu(msg)*d1 + e1)*d2 ; out = w0*pois + w1*e1 + w2*e2
//          (e1 read back from embs_h, fp16)
template<int LAYER>
__global__ void __launch_bounds__(256) spmm_src_fused_kernel(
    const int*  __restrict__ ptr,
    const int2* __restrict__ pairs,
    const __half* __restrict__ dense,   // msg_tar_h
    const float4* __restrict__ d1,
    const float4* __restrict__ d2,
    const uint4*  __restrict__ prev_h,  // embs_h (LAYER 1)
    const float4* __restrict__ pois,
    float4* __restrict__ outp,          // out (LAYER 1)
    uint4*  __restrict__ out_h)         // embs_h (LAYER 0)
{
    int row = (blockIdx.x * 256 + threadIdx.x) >> 5;
    if (row >= N_POIS) return;
    int lane = threadIdx.x & 31;
    float4 a0 = make_float4(0.f, 0.f, 0.f, 0.f), a1 = a0;
    gather_row_h(ptr, pairs, dense, row, lane, a0, a1);

    size_t i0 = (size_t)row * (D / 4) + 2 * lane;   // float4 pair for [lane*8, +8)
    float4 m0 = __ldcs(d1 + i0),  m1 = __ldcs(d1 + i0 + 1);
    float4 q0 = __ldcs(d2 + i0),  q1 = __ldcs(d2 + i0 + 1);

    float4 p0, p1;
    if (LAYER == 0) {
        p0 = __ldg(pois + i0); p1 = __ldg(pois + i0 + 1);
    } else {
        uint4 u = __ldg(prev_h + (size_t)row * (D / 8) + lane);
        float2 f0 = unpack2(u.x), f1 = unpack2(u.y);
        float2 f2 = unpack2(u.z), f3 = unpack2(u.w);
        p0 = make_float4(f0.x, f0.y, f1.x, f1.y);
        p1 = make_float4(f2.x, f2.y, f3.x, f3.y);
    }

    float4 e0, e1;
    e0.x = (fmaxf(a0.x, 0.f) * m0.x + p0.x) * q0.x;
    e0.y = (fmaxf(a0.y, 0.f) * m0.y + p0.y) * q0.y;
    e0.z = (fmaxf(a0.z, 0.f) * m0.z + p0.z) * q0.z;
    e0.w = (fmaxf(a0.w, 0.f) * m0.w + p0.w) * q0.w;
    e1.x = (fmaxf(a1.x, 0.f) * m1.x + p1.x) * q1.x;
    e1.y = (fmaxf(a1.y, 0.f) * m1.y + p1.y) * q1.y;
    e1.z = (fmaxf(a1.z, 0.f) * m1.z + p1.z) * q1.z;
    e1.w = (fmaxf(a1.w, 0.f) * m1.w + p1.w) * q1.w;

    if (LAYER == 0) {
        uint4 h;
        h.x = pack2(e0.x, e0.y); h.y = pack2(e0.z, e0.w);
        h.z = pack2(e1.x, e1.y); h.w = pack2(e1.z, e1.w);
        out_h[(size_t)row * (D / 8) + lane] = h;    // linear
    } else {
        float w0 = g_w[0], w1 = g_w[1], w2 = g_w[2];
        float4 z0 = __ldcs(pois + i0), z1 = __ldcs(pois + i0 + 1);
        float4 o0, o1;
        o0.x = w0 * z0.x + w1 * p0.x + w2 * e0.x;
        o0.y = w0 * z0.y + w1 * p0.y + w2 * e0.y;
        o0.z = w0 * z0.z + w1 * p0.z + w2 * e0.z;
        o0.w = w0 * z0.w + w1 * p0.w + w2 * e0.w;
        o1.x = w0 * z1.x + w1 * p1.x + w2 * e1.x;
        o1.y = w0 * z1.y + w1 * p1.y + w2 * e1.y;
        o1.z = w0 * z1.z + w1 * p1.z + w2 * e1.z;
        o1.w = w0 * z1.w + w1 * p1.w + w2 * e1.w;
        outp[i0]     = o0;
        outp[i0 + 1] = o1;
    }
}

// ---------------------------------------------------------------------------
extern "C" void kernel_launch(void* const* d_in, const int* in_sizes, int n_in,
                              void* d_out, int out_size)
{
    const float* pois      = (const float*)d_in[0];
    const float* tar_vals  = (const float*)d_in[1];
    const float* src_vals  = (const float*)d_in[2];
    const float* attn      = (const float*)d_in[3];
    const float* drop1     = (const float*)d_in[4];
    const float* drop2     = (const float*)d_in[5];
    const int*   tar_rows  = (const int*)d_in[6];
    const int*   tar_cols  = (const int*)d_in[7];
    const int*   src_rows  = (const int*)d_in[8];
    const int*   src_cols  = (const int*)d_in[9];
    float*       out       = (float*)d_out;

    __half *pois_h, *msg_tar_h, *embs_h;
    int *ptr_tar, *cur_tar, *ptr_src, *cur_src, *bsums;
    int2 *pairs_tar, *pairs_src;
    cudaGetSymbolAddress((void**)&pois_h,    g_pois_h);
    cudaGetSymbolAddress((void**)&msg_tar_h, g_msg_tar_h);
    cudaGetSymbolAddress((void**)&embs_h,    g_embs_h);
    cudaGetSymbolAddress((void**)&ptr_tar,   g_ptr_tar);
    cudaGetSymbolAddress((void**)&cur_tar,   g_cur_tar);
    cudaGetSymbolAddress((void**)&pairs_tar, g_pairs_tar);
    cudaGetSymbolAddress((void**)&ptr_src,   g_ptr_src);
    cudaGetSymbolAddress((void**)&cur_src,   g_cur_src);
    cudaGetSymbolAddress((void**)&pairs_src, g_pairs_src);
    cudaGetSymbolAddress((void**)&bsums,     g_bsums);

    const int nnz_blocks = (NNZ + 255) / 256;
    const size_t ld = (size_t)N_POIS * D;

    softmax_w_kernel<<<1, 1>>>(attn);

    // fp16 copy of pois (needed before layer-0 tar spmm)
    tohalf_kernel<<<(N_POIS * D / 8 + 255) / 256, 256>>>(
        (const float4*)pois, (uint4*)pois_h, N_POIS * D / 8);

    // ---- fused CSR build (tar + src) ----
    zero_both_kernel<<<(N_POIS + 1 + 255) / 256, 256>>>(ptr_tar, N_HE + 1,
                                                        ptr_src, N_POIS + 1);
    hist_both_kernel<<<nnz_blocks, 256>>>(tar_rows, src_rows, ptr_tar, ptr_src);
    scanA_kernel<<<2 * NB, 256>>>(ptr_tar, N_HE + 1, ptr_src, N_POIS + 1, bsums);
    scanB_kernel<<<2, NB>>>(bsums);
    scanC_kernel<<<2 * NB, 256>>>(ptr_tar, N_HE + 1, ptr_src, N_POIS + 1, bsums,
                                  cur_tar, cur_src);
    scatter_both_kernel<<<nnz_blocks, 256>>>(
        tar_rows, tar_cols, tar_vals, cur_tar, pairs_tar,
        src_rows, src_cols, src_vals, cur_src, pairs_src);

    const int tar_blocks = (N_HE * 32 + 255) / 256;
    const int src_blocks = (N_POIS * 32 + 255) / 256;

    // ---- layer 0 ----
    spmm_tar_kernel<<<tar_blocks, 256>>>(ptr_tar, pairs_tar, pois_h, msg_tar_h);
    spmm_src_fused_kernel<0><<<src_blocks, 256>>>(ptr_src, pairs_src, msg_tar_h,
        (const float4*)drop1, (const float4*)drop2,
        nullptr, (const float4*)pois, nullptr, (uint4*)embs_h);

    // ---- layer 1 ----
    spmm_tar_kernel<<<tar_blocks, 256>>>(ptr_tar, pairs_tar, embs_h, msg_tar_h);
    spmm_src_fused_kernel<1><<<src_blocks, 256>>>(ptr_src, pairs_src, msg_tar_h,
        (const float4*)(drop1 + ld), (const float4*)(drop2 + ld),
        (const uint4*)embs_h, (const float4*)pois,
        (float4*)out, nullptr);
}

// round 6
// speedup vs baseline: 3.6478x; 1.0896x over previous
#include <cuda_runtime.h>
#include <cuda_fp16.h>

#define N_POIS 100000
#define N_HE   50000
#define NNZ    1600000
#define D      256
#define NB     128          // scan blocks per matrix

// ---------------- scratch (allocation-free device globals) ----------------
__device__ __half g_pois_h[(size_t)N_POIS * D];   // 51.2 MB fp16 gather copy
__device__ __half g_msg_tar_h[(size_t)N_HE * D];  // 25.6 MB fp16 intermediate
__device__ __half g_embs_h[(size_t)N_POIS * D];   // 51.2 MB fp16 e1
__device__ float  g_w[3];

__device__ int  g_ptr_tar[N_HE + 1];
__device__ int  g_cur_tar[N_HE];
__device__ int2 g_pairs_tar[NNZ];
__device__ int  g_ptr_src[N_POIS + 1];
__device__ int  g_cur_src[N_POIS];
__device__ int2 g_pairs_src[NNZ];
__device__ int  g_bsums[2 * NB];

// ---------------------------------------------------------------------------
__device__ __forceinline__ unsigned pack2(float x, float y) {
    __half2 h = __floats2half2_rn(x, y);
    return *reinterpret_cast<unsigned*>(&h);
}
__device__ __forceinline__ float2 unpack2(unsigned u) {
    __half2 h = *reinterpret_cast<__half2*>(&u);
    return __half22float2(h);
}

// ---------------------------------------------------------------------------
__global__ void softmax_w_kernel(const float* __restrict__ attn) {
    float a0 = attn[0], a1 = attn[1], a2 = attn[2];
    float m = fmaxf(a0, fmaxf(a1, a2));
    float e0 = expf(a0 - m), e1 = expf(a1 - m), e2 = expf(a2 - m);
    float inv = 1.0f / (e0 + e1 + e2);
    g_w[0] = e0 * inv; g_w[1] = e1 * inv; g_w[2] = e2 * inv;
}

__global__ void __launch_bounds__(256) zero_both_kernel(int* __restrict__ a, int na,
                                                        int* __restrict__ b, int nb) {
    int i = blockIdx.x * 256 + threadIdx.x;
    if (i < na) a[i] = 0;
    if (i < nb) b[i] = 0;
}

// 4 edges per thread, int4 loads (NNZ % 4 == 0)
__global__ void __launch_bounds__(256) hist_both_kernel(const int4* __restrict__ rt,
                                                        const int4* __restrict__ rs,
                                                        int* __restrict__ ct,
                                                        int* __restrict__ cs) {
    int e = blockIdx.x * 256 + threadIdx.x;
    if (e >= NNZ / 4) return;
    int4 a = __ldcs(rt + e);
    int4 b = __ldcs(rs + e);
    atomicAdd(&ct[a.x + 1], 1); atomicAdd(&ct[a.y + 1], 1);
    atomicAdd(&ct[a.z + 1], 1); atomicAdd(&ct[a.w + 1], 1);
    atomicAdd(&cs[b.x + 1], 1); atomicAdd(&cs[b.y + 1], 1);
    atomicAdd(&cs[b.z + 1], 1); atomicAdd(&cs[b.w + 1], 1);
}

// ---- fused multi-block scan over both ptr arrays ----
__global__ void __launch_bounds__(256) scanA_kernel(int* __restrict__ pt, int lt,
                                                    int* __restrict__ ps, int ls,
                                                    int* __restrict__ bsums) {
    __shared__ int red[256];
    int m   = blockIdx.x / NB;
    int blk = blockIdx.x % NB;
    int* p  = m ? ps : pt;
    int len = m ? ls : lt;
    int chunk = (len + NB - 1) / NB;
    int lo = blk * chunk, hi = min(len, lo + chunk);
    int sub = (chunk + 255) >> 8;
    int a = lo + threadIdx.x * sub, b = min(hi, a + sub);
    int s = 0;
    for (int i = a; i < b; i++) s += p[i];
    red[threadIdx.x] = s;
    __syncthreads();
    for (int d = 128; d > 0; d >>= 1) {
        if (threadIdx.x < d) red[threadIdx.x] += red[threadIdx.x + d];
        __syncthreads();
    }
    if (threadIdx.x == 0) bsums[blockIdx.x] = red[0];
}

__global__ void __launch_bounds__(NB) scanB_kernel(int* __restrict__ bsums) {
    __shared__ int s[NB];
    int t = threadIdx.x;
    int* bs = bsums + blockIdx.x * NB;
    s[t] = bs[t];
    __syncthreads();
    int acc = s[t];
    for (int d = 1; d < NB; d <<= 1) {
        int v = (t >= d) ? s[t - d] : 0;
        __syncthreads();
        s[t] = acc = acc + v;
        __syncthreads();
        acc = s[t];
    }
    bs[t] = (t == 0) ? 0 : s[t - 1];   // exclusive
}

__global__ void __launch_bounds__(256) scanC_kernel(int* __restrict__ pt, int lt,
                                                    int* __restrict__ ps, int ls,
                                                    const int* __restrict__ bsums,
                                                    int* __restrict__ curt,
                                                    int* __restrict__ curs) {
    __shared__ int s[256];
    int m   = blockIdx.x / NB;
    int blk = blockIdx.x % NB;
    int* p   = m ? ps : pt;
    int len  = m ? ls : lt;
    int* cur = m ? curs : curt;
    int chunk = (len + NB - 1) / NB;
    int lo = blk * chunk, hi = min(len, lo + chunk);
    int sub = (chunk + 255) >> 8;
    int a = lo + threadIdx.x * sub, b = min(hi, a + sub);
    int t = threadIdx.x;
    int sum = 0;
    for (int i = a; i < b; i++) sum += p[i];
    s[t] = sum;
    __syncthreads();
    int acc = s[t];
    for (int d = 1; d < 256; d <<= 1) {
        int v = (t >= d) ? s[t - d] : 0;
        __syncthreads();
        s[t] = acc = acc + v;
        __syncthreads();
        acc = s[t];
    }
    int off = bsums[blockIdx.x] + ((t == 0) ? 0 : s[t - 1]);
    for (int i = a; i < b; i++) {
        off += p[i];
        p[i] = off;
        if (i < len - 1) cur[i] = off;    // cur[row] = ptr[row]
    }
}

// 4 edges per thread, vector loads
__global__ void __launch_bounds__(256) scatter_both_kernel(
    const int4* __restrict__ rt, const int4* __restrict__ colt,
    const float4* __restrict__ valt, int* __restrict__ curt, int2* __restrict__ pt,
    const int4* __restrict__ rs, const int4* __restrict__ cols,
    const float4* __restrict__ vals, int* __restrict__ curs, int2* __restrict__ ps)
{
    int e = blockIdx.x * 256 + threadIdx.x;
    if (e >= NNZ / 4) return;
    {
        int4   r = __ldcs(rt + e);
        int4   c = __ldcs(colt + e);
        float4 v = __ldcs(valt + e);
        pt[atomicAdd(&curt[r.x], 1)] = make_int2(c.x, __float_as_int(v.x));
        pt[atomicAdd(&curt[r.y], 1)] = make_int2(c.y, __float_as_int(v.y));
        pt[atomicAdd(&curt[r.z], 1)] = make_int2(c.z, __float_as_int(v.z));
        pt[atomicAdd(&curt[r.w], 1)] = make_int2(c.w, __float_as_int(v.w));
    }
    {
        int4   r = __ldcs(rs + e);
        int4   c = __ldcs(cols + e);
        float4 v = __ldcs(vals + e);
        ps[atomicAdd(&curs[r.x], 1)] = make_int2(c.x, __float_as_int(v.x));
        ps[atomicAdd(&curs[r.y], 1)] = make_int2(c.y, __float_as_int(v.y));
        ps[atomicAdd(&curs[r.z], 1)] = make_int2(c.z, __float_as_int(v.z));
        ps[atomicAdd(&curs[r.w], 1)] = make_int2(c.w, __float_as_int(v.w));
    }
}

// fp32 -> fp16 copy (8 elems/thread), LINEAR layout
__global__ void __launch_bounds__(256) tohalf_kernel(const float4* __restrict__ in,
                                                     uint4* __restrict__ out, int n8) {
    int i = blockIdx.x * 256 + threadIdx.x;
    if (i >= n8) return;
    float4 a = __ldcs(in + 2 * i), b = __ldcs(in + 2 * i + 1);
    uint4 o;
    o.x = pack2(a.x, a.y); o.y = pack2(a.z, a.w);
    o.z = pack2(b.x, b.y); o.w = pack2(b.z, b.w);
    out[i] = o;
}

// ---------------------------------------------------------------------------
// fp16 gather: warp per row; lane owns CONTIGUOUS elements [lane*8, lane*8+8).
// Pairs are read as uniform broadcast loads (all lanes same address, L1-hit).
__device__ __forceinline__ void gather_row_h(const int* __restrict__ ptr,
                                             const int2* __restrict__ pairs,
                                             const __half* __restrict__ dense,
                                             int row, int lane,
                                             float4& a0, float4& a1) {
    int start = __ldg(ptr + row), end = __ldg(ptr + row + 1);
    #pragma unroll 4
    for (int j = start; j < end; j++) {
        int2 pr = __ldg(pairs + j);                 // uniform across warp
        float v = __int_as_float(pr.y);
        uint4 u = __ldg(reinterpret_cast<const uint4*>(dense + (size_t)pr.x * D) + lane);
        float2 f0 = unpack2(u.x), f1 = unpack2(u.y);
        float2 f2 = unpack2(u.z), f3 = unpack2(u.w);
        a0.x = fmaf(v, f0.x, a0.x); a0.y = fmaf(v, f0.y, a0.y);
        a0.z = fmaf(v, f1.x, a0.z); a0.w = fmaf(v, f1.y, a0.w);
        a1.x = fmaf(v, f2.x, a1.x); a1.y = fmaf(v, f2.y, a1.y);
        a1.z = fmaf(v, f3.x, a1.z); a1.w = fmaf(v, f3.y, a1.w);
    }
}

__global__ void __launch_bounds__(256) spmm_tar_kernel(const int*  __restrict__ ptr,
                                                       const int2* __restrict__ pairs,
                                                       const __half* __restrict__ dense,
                                                       __half* __restrict__ out) {
    int row = (blockIdx.x * 256 + threadIdx.x) >> 5;
    if (row >= N_HE) return;
    int lane = threadIdx.x & 31;
    float4 a0 = make_float4(0.f, 0.f, 0.f, 0.f), a1 = a0;
    gather_row_h(ptr, pairs, dense, row, lane, a0, a1);
    uint4 o;
    o.x = pack2(a0.x, a0.y); o.y = pack2(a0.z, a0.w);
    o.z = pack2(a1.x, a1.y); o.w = pack2(a1.z, a1.w);
    *(reinterpret_cast<uint4*>(out + (size_t)row * D) + lane) = o;   // linear
}

// Fused src-SpMM + epilogue.  a0/a1 are elements [lane*8, lane*8+8).
// LAYER 0: e1 = (relu(msg)*d1 + pois)*d2 ; embs_h = fp16(e1)   (pois from fp16)
// LAYER 1: e2 = (relu(msg)*d1 + e1)*d2 ; out = w0*pois + w1*e1 + w2*e2
template<int LAYER>
__global__ void __launch_bounds__(256) spmm_src_fused_kernel(
    const int*  __restrict__ ptr,
    const int2* __restrict__ pairs,
    const __half* __restrict__ dense,   // msg_tar_h
    const float4* __restrict__ d1,
    const float4* __restrict__ d2,
    const uint4*  __restrict__ prev_h,  // L0: pois_h ; L1: embs_h
    const uint4*  __restrict__ pois_h,  // L1 only
    float4* __restrict__ outp,          // L1: out
    uint4*  __restrict__ out_h)         // L0: embs_h
{
    int row = (blockIdx.x * 256 + threadIdx.x) >> 5;
    if (row >= N_POIS) return;
    int lane = threadIdx.x & 31;
    float4 a0 = make_float4(0.f, 0.f, 0.f, 0.f), a1 = a0;
    gather_row_h(ptr, pairs, dense, row, lane, a0, a1);

    size_t i0 = (size_t)row * (D / 4) + 2 * lane;   // float4 pair for [lane*8, +8)
    size_t ih = (size_t)row * (D / 8) + lane;
    float4 m0 = __ldcs(d1 + i0),  m1 = __ldcs(d1 + i0 + 1);
    float4 q0 = __ldcs(d2 + i0),  q1 = __ldcs(d2 + i0 + 1);

    float4 p0, p1;
    {
        uint4 u = __ldg(prev_h + ih);
        float2 f0 = unpack2(u.x), f1 = unpack2(u.y);
        float2 f2 = unpack2(u.z), f3 = unpack2(u.w);
        p0 = make_float4(f0.x, f0.y, f1.x, f1.y);
        p1 = make_float4(f2.x, f2.y, f3.x, f3.y);
    }

    float4 e0, e1;
    e0.x = (fmaxf(a0.x, 0.f) * m0.x + p0.x) * q0.x;
    e0.y = (fmaxf(a0.y, 0.f) * m0.y + p0.y) * q0.y;
    e0.z = (fmaxf(a0.z, 0.f) * m0.z + p0.z) * q0.z;
    e0.w = (fmaxf(a0.w, 0.f) * m0.w + p0.w) * q0.w;
    e1.x = (fmaxf(a1.x, 0.f) * m1.x + p1.x) * q1.x;
    e1.y = (fmaxf(a1.y, 0.f) * m1.y + p1.y) * q1.y;
    e1.z = (fmaxf(a1.z, 0.f) * m1.z + p1.z) * q1.z;
    e1.w = (fmaxf(a1.w, 0.f) * m1.w + p1.w) * q1.w;

    if (LAYER == 0) {
        uint4 h;
        h.x = pack2(e0.x, e0.y); h.y = pack2(e0.z, e0.w);
        h.z = pack2(e1.x, e1.y); h.w = pack2(e1.z, e1.w);
        out_h[ih] = h;    // linear
    } else {
        float w0 = g_w[0], w1 = g_w[1], w2 = g_w[2];
        float4 z0, z1;
        {
            uint4 u = __ldg(pois_h + ih);
            float2 f0 = unpack2(u.x), f1 = unpack2(u.y);
            float2 f2 = unpack2(u.z), f3 = unpack2(u.w);
            z0 = make_float4(f0.x, f0.y, f1.x, f1.y);
            z1 = make_float4(f2.x, f2.y, f3.x, f3.y);
        }
        float4 o0, o1;
        o0.x = w0 * z0.x + w1 * p0.x + w2 * e0.x;
        o0.y = w0 * z0.y + w1 * p0.y + w2 * e0.y;
        o0.z = w0 * z0.z + w1 * p0.z + w2 * e0.z;
        o0.w = w0 * z0.w + w1 * p0.w + w2 * e0.w;
        o1.x = w0 * z1.x + w1 * p1.x + w2 * e1.x;
        o1.y = w0 * z1.y + w1 * p1.y + w2 * e1.y;
        o1.z = w0 * z1.z + w1 * p1.z + w2 * e1.z;
        o1.w = w0 * z1.w + w1 * p1.w + w2 * e1.w;
        outp[i0]     = o0;
        outp[i0 + 1] = o1;
    }
}

// ---------------------------------------------------------------------------
extern "C" void kernel_launch(void* const* d_in, const int* in_sizes, int n_in,
                              void* d_out, int out_size)
{
    const float* pois      = (const float*)d_in[0];
    const float* tar_vals  = (const float*)d_in[1];
    const float* src_vals  = (const float*)d_in[2];
    const float* attn      = (const float*)d_in[3];
    const float* drop1     = (const float*)d_in[4];
    const float* drop2     = (const float*)d_in[5];
    const int*   tar_rows  = (const int*)d_in[6];
    const int*   tar_cols  = (const int*)d_in[7];
    const int*   src_rows  = (const int*)d_in[8];
    const int*   src_cols  = (const int*)d_in[9];
    float*       out       = (float*)d_out;

    __half *pois_h, *msg_tar_h, *embs_h;
    int *ptr_tar, *cur_tar, *ptr_src, *cur_src, *bsums;
    int2 *pairs_tar, *pairs_src;
    cudaGetSymbolAddress((void**)&pois_h,    g_pois_h);
    cudaGetSymbolAddress((void**)&msg_tar_h, g_msg_tar_h);
    cudaGetSymbolAddress((void**)&embs_h,    g_embs_h);
    cudaGetSymbolAddress((void**)&ptr_tar,   g_ptr_tar);
    cudaGetSymbolAddress((void**)&cur_tar,   g_cur_tar);
    cudaGetSymbolAddress((void**)&pairs_tar, g_pairs_tar);
    cudaGetSymbolAddress((void**)&ptr_src,   g_ptr_src);
    cudaGetSymbolAddress((void**)&cur_src,   g_cur_src);
    cudaGetSymbolAddress((void**)&pairs_src, g_pairs_src);
    cudaGetSymbolAddress((void**)&bsums,     g_bsums);

    const int nnz4_blocks = (NNZ / 4 + 255) / 256;
    const size_t ld = (size_t)N_POIS * D;

    softmax_w_kernel<<<1, 1>>>(attn);

    // ---- fused CSR build (tar + src) ----
    zero_both_kernel<<<(N_POIS + 1 + 255) / 256, 256>>>(ptr_tar, N_HE + 1,
                                                        ptr_src, N_POIS + 1);
    hist_both_kernel<<<nnz4_blocks, 256>>>((const int4*)tar_rows, (const int4*)src_rows,
                                           ptr_tar, ptr_src);
    scanA_kernel<<<2 * NB, 256>>>(ptr_tar, N_HE + 1, ptr_src, N_POIS + 1, bsums);
    scanB_kernel<<<2, NB>>>(bsums);
    scanC_kernel<<<2 * NB, 256>>>(ptr_tar, N_HE + 1, ptr_src, N_POIS + 1, bsums,
                                  cur_tar, cur_src);
    scatter_both_kernel<<<nnz4_blocks, 256>>>(
        (const int4*)tar_rows, (const int4*)tar_cols, (const float4*)tar_vals,
        cur_tar, pairs_tar,
        (const int4*)src_rows, (const int4*)src_cols, (const float4*)src_vals,
        cur_src, pairs_src);

    // fp16 copy of pois — placed after CSR build so pois_h is L2-warm for layer 0
    tohalf_kernel<<<(N_POIS * D / 8 + 255) / 256, 256>>>(
        (const float4*)pois, (uint4*)pois_h, N_POIS * D / 8);

    const int tar_blocks = (N_HE * 32 + 255) / 256;
    const int src_blocks = (N_POIS * 32 + 255) / 256;

    // ---- layer 0 ----
    spmm_tar_kernel<<<tar_blocks, 256>>>(ptr_tar, pairs_tar, pois_h, msg_tar_h);
    spmm_src_fused_kernel<0><<<src_blocks, 256>>>(ptr_src, pairs_src, msg_tar_h,
        (const float4*)drop1, (const float4*)drop2,
        (const uint4*)pois_h, nullptr, nullptr, (uint4*)embs_h);

    // ---- layer 1 ----
    spmm_tar_kernel<<<tar_blocks, 256>>>(ptr_tar, pairs_tar, embs_h, msg_tar_h);
    spmm_src_fused_kernel<1><<<src_blocks, 256>>>(ptr_src, pairs_src, msg_tar_h,
        (const float4*)(drop1 + ld), (const float4*)(drop2 + ld),
        (const uint4*)embs_h, (const uint4*)pois_h,
        (float4*)out, nullptr);
}